// round 7
// baseline (speedup 1.0000x reference)
#include <cuda_runtime.h>

#define B_ROWS   16384
#define NFEAT    1024
#define FACTORS  64
#define TOTAL    524288
#define STRIDE   128            // max row count ~57 (binomial, 17-sigma safe)

// ---------------------------------------------------------------------------
// Scratch (device globals; BSS-zeroed at load, self-cleaned every launch)
// ---------------------------------------------------------------------------
__device__ int            g_counts[B_ROWS];
__device__ unsigned short g_sorted[B_ROWS * STRIDE];   // feat ids, by batch row

// G table (256 KB) is hot -> pin in L1.
__device__ __forceinline__ float2 ldg_el2(const float* p) {
    float2 v;
    asm("ld.global.nc.L1::evict_last.v2.f32 {%0,%1}, [%2];"
        : "=f"(v.x), "=f"(v.y) : "l"(p));
    return v;
}

// ---------------------------------------------------------------------------
// 1) bucket scatter: 4 independent atomic+store chains per thread.
//    Also zeroes the output accumulator (runs before compute in stream order).
// ---------------------------------------------------------------------------
__global__ __launch_bounds__(256) void scatter_kernel(
    const int* __restrict__ sample_idx,
    const int* __restrict__ feat_idx,
    float*     __restrict__ out)
{
    if (blockIdx.x == 0 && threadIdx.x == 0) out[0] = 0.0f;

    const int base = (blockIdx.x * 256 + threadIdx.x) * 4;
    const int4 s = __ldg((const int4*)(sample_idx + base));
    const int4 f = __ldg((const int4*)(feat_idx + base));

    const int p0 = atomicAdd(&g_counts[s.x], 1);
    const int p1 = atomicAdd(&g_counts[s.y], 1);
    const int p2 = atomicAdd(&g_counts[s.z], 1);
    const int p3 = atomicAdd(&g_counts[s.w], 1);

    if (p0 < STRIDE) g_sorted[s.x * STRIDE + p0] = (unsigned short)f.x;
    if (p1 < STRIDE) g_sorted[s.y * STRIDE + p1] = (unsigned short)f.y;
    if (p2 < STRIDE) g_sorted[s.z * STRIDE + p2] = (unsigned short)f.z;
    if (p3 < STRIDE) g_sorted[s.w * STRIDE + p3] = (unsigned short)f.w;
}

// ---------------------------------------------------------------------------
// 2) compute: one warp per batch row b.
//    w_b = sum over row's items of K[u,n] * G[n]  (2 floats per lane)
//    result += H[u] . w_b                          (ONE H dot per b)
//    Resets g_counts[b] to 0 so the next replay sees a clean state.
// ---------------------------------------------------------------------------
__global__ __launch_bounds__(256) void compute_kernel(
    const int*   __restrict__ user,
    const float* __restrict__ H,
    const float* __restrict__ G,
    const float* __restrict__ K,
    float*       __restrict__ out)
{
    const int lane = threadIdx.x & 31;
    const int wid  = threadIdx.x >> 5;
    const int b    = blockIdx.x * 8 + wid;        // 2048 x 8 = 16384 rows

    const int u   = __ldg(user + b);
    const int cnt = min(g_counts[b], STRIDE);
    if (lane == 0) g_counts[b] = 0;               // self-clean for next replay

    const float* __restrict__ Krow = K + (u << 10);
    const unsigned short* __restrict__ row = g_sorted + b * STRIDE;

    float wx = 0.0f, wy = 0.0f;                   // w[2*lane], w[2*lane+1]
    const float* Gl = G + 2 * lane;

    for (int base = 0; base < cnt; base += 32) {
        const int c = min(32, cnt - base);
        int   n  = 0;
        float kv = 0.0f;
        if (lane < c) {
            n  = (int)row[base + lane];           // coalesced u16
            kv = __ldg(Krow + n);                 // clustered in one 4KB K row
        }

        int j = 0;
        for (; j + 8 <= c; j += 8) {              // 8 independent LDGs in flight
            #pragma unroll
            for (int k = 0; k < 8; ++k) {
                const int   nj  = __shfl_sync(0xFFFFFFFFu, n,  j + k);
                const float kvj = __shfl_sync(0xFFFFFFFFu, kv, j + k);
                const float2 g  = ldg_el2(Gl + (nj << 6));
                wx = fmaf(kvj, g.x, wx);
                wy = fmaf(kvj, g.y, wy);
            }
        }
        for (; j < c; ++j) {
            const int   nj  = __shfl_sync(0xFFFFFFFFu, n,  j);
            const float kvj = __shfl_sync(0xFFFFFFFFu, kv, j);
            const float2 g  = ldg_el2(Gl + (nj << 6));
            wx = fmaf(kvj, g.x, wx);
            wy = fmaf(kvj, g.y, wy);
        }
    }

    // one H-row load + dot per b
    const float2 h = *(const float2*)(H + (u << 6) + 2 * lane);
    float r = fmaf(wx, h.x, wy * h.y);

    #pragma unroll
    for (int off = 16; off > 0; off >>= 1)
        r += __shfl_xor_sync(0xFFFFFFFFu, r, off);

    __shared__ float warp_sums[8];
    if (lane == 0) warp_sums[wid] = r;
    __syncthreads();
    if (wid == 0) {
        float v = (lane < 8) ? warp_sums[lane] : 0.0f;
        #pragma unroll
        for (int off = 4; off > 0; off >>= 1)
            v += __shfl_xor_sync(0xFFFFFFFFu, v, off);
        if (lane == 0) atomicAdd(out, v);
    }
}

// ---------------------------------------------------------------------------
extern "C" void kernel_launch(void* const* d_in, const int* in_sizes, int n_in,
                              void* d_out, int out_size)
{
    const int*   user       = (const int*)  d_in[0];
    const int*   sample_idx = (const int*)  d_in[1];
    const int*   feat_idx   = (const int*)  d_in[2];
    const float* H          = (const float*)d_in[3];
    const float* G          = (const float*)d_in[4];
    const float* K          = (const float*)d_in[5];
    float*       out        = (float*)d_out;

    (void)in_sizes; (void)n_in; (void)out_size;

    scatter_kernel<<<TOTAL / 4 / 256, 256>>>(sample_idx, feat_idx, out);
    compute_kernel<<<B_ROWS / 8, 256>>>(user, H, G, K, out);
}